// round 3
// baseline (speedup 1.0000x reference)
#include <cuda_runtime.h>

#define CROP 14
#define B_ 4
#define N_ 256
#define H_ 256
#define W_ 256
#define C_ 256
#define CQ (C_ / 4)          // float4 quads per pixel = 64

// 196 positions per box, split across 7 CTAs of 28 positions each.
#define PARTS 7
#define POS_PER_PART 28

__global__ __launch_bounds__(256) void roi_align_kernel(
    const float* __restrict__ boxes,
    const float* __restrict__ fpn,
    float* __restrict__ out)
{
    // Phase-1: per-axis sampling grids
    __shared__ int   s_i0[2][CROP];
    __shared__ int   s_i1[2][CROP];
    __shared__ float s_w [2][CROP];
    __shared__ float s_v [2][CROP];
    // Phase-2: per-position gmem offsets (in float4 units) + combined weights
    __shared__ int   s_otl[POS_PER_PART], s_otr[POS_PER_PART];
    __shared__ int   s_obl[POS_PER_PART], s_obr[POS_PER_PART];
    __shared__ float s_w00[POS_PER_PART], s_w01[POS_PER_PART];
    __shared__ float s_w10[POS_PER_PART], s_w11[POS_PER_PART];

    const int blk  = blockIdx.y;       // box index: b * N_ + n (box-major)
    const int part = blockIdx.x;       // 0..6
    const int b    = blk >> 8;
    const int base = part * POS_PER_PART;

    const float4 bx = ((const float4*)boxes)[blk];   // (x1, y1, x2, y2)

    const int tid = threadIdx.x;
    if (tid < 2 * CROP) {
        const int axis = tid / CROP;   // 0 = y, 1 = x
        const int i    = tid % CROP;
        const float lo = (axis == 0) ? bx.y : bx.x;
        const float hi = (axis == 0) ? bx.w : bx.z;
        // Replicate reference math in float32:
        //   n1 = lo/255 ; n2 = (hi-1)/255 ; t = i/13 ; s = (n1 + (n2-n1)*t) * 255
        const float t  = (float)i / 13.0f;
        const float n1 = lo / 255.0f;
        const float n2 = (hi - 1.0f) / 255.0f;
        const float s  = (n1 + (n2 - n1) * t) * 255.0f;
        const float valid = (s >= 0.0f && s <= 255.0f) ? 1.0f : 0.0f;
        const float f0 = floorf(s);
        const float w  = s - f0;
        int i0 = (int)f0;
        int i1 = i0 + 1;
        i0 = min(max(i0, 0), H_ - 1);
        i1 = min(max(i1, 0), H_ - 1);
        s_i0[axis][i] = i0;
        s_i1[axis][i] = i1;
        s_w [axis][i] = w;
        s_v [axis][i] = valid;
    }
    __syncthreads();

    if (tid < POS_PER_PART) {
        const int pos = base + tid;
        const int py  = pos / CROP;
        const int px  = pos - py * CROP;
        const int   y0 = s_i0[0][py], y1 = s_i1[0][py];
        const int   x0 = s_i0[1][px], x1 = s_i1[1][px];
        const float wy = s_w[0][py],  wx = s_w[1][px];
        const float v  = s_v[0][py] * s_v[1][px];
        s_otl[tid] = (y0 * W_ + x0) * CQ;
        s_otr[tid] = (y0 * W_ + x1) * CQ;
        s_obl[tid] = (y1 * W_ + x0) * CQ;
        s_obr[tid] = (y1 * W_ + x1) * CQ;
        s_w00[tid] = (1.0f - wy) * (1.0f - wx) * v;
        s_w01[tid] = (1.0f - wy) * wx * v;
        s_w10[tid] = wy * (1.0f - wx) * v;
        s_w11[tid] = wy * wx * v;
    }
    __syncthreads();

    const float4* img  = (const float4*)(fpn) + (size_t)b * (H_ * W_ * CQ);
    float4*       outp = (float4*)(out) + ((size_t)blk * (CROP * CROP) + base) * CQ;

    const int sub = tid >> 6;   // 4 positions in flight
    const int q   = tid & 63;   // float4 index within C

    // Software pipeline, prefetch distance 1: 8 LDG.128 in flight per thread.
    int p = sub;
    float4 tl = img[s_otl[p] + q];
    float4 tr = img[s_otr[p] + q];
    float4 bl = img[s_obl[p] + q];
    float4 br = img[s_obr[p] + q];

    #pragma unroll
    for (int i = 0; i < POS_PER_PART / 4; i++) {
        const int pn = p + 4;
        float4 ntl, ntr, nbl, nbr;
        if (i < POS_PER_PART / 4 - 1) {
            ntl = img[s_otl[pn] + q];
            ntr = img[s_otr[pn] + q];
            nbl = img[s_obl[pn] + q];
            nbr = img[s_obr[pn] + q];
        }

        const float w00 = s_w00[p];
        const float w01 = s_w01[p];
        const float w10 = s_w10[p];
        const float w11 = s_w11[p];

        float4 r;
        r.x = tl.x * w00 + tr.x * w01 + bl.x * w10 + br.x * w11;
        r.y = tl.y * w00 + tr.y * w01 + bl.y * w10 + br.y * w11;
        r.z = tl.z * w00 + tr.z * w01 + bl.z * w10 + br.z * w11;
        r.w = tl.w * w00 + tr.w * w01 + bl.w * w10 + br.w * w11;

        // Streaming store: output is never re-read; keep the image L2-resident.
        __stcs(&outp[p * CQ + q], r);

        p  = pn;
        tl = ntl; tr = ntr; bl = nbl; br = nbr;
    }
}

extern "C" void kernel_launch(void* const* d_in, const int* in_sizes, int n_in,
                              void* d_out, int out_size) {
    const float* boxes = (const float*)d_in[0];
    const float* fpn   = (const float*)d_in[1];
    if (n_in >= 2 && in_sizes[0] > in_sizes[1]) {
        boxes = (const float*)d_in[1];
        fpn   = (const float*)d_in[0];
    }
    dim3 grid(PARTS, B_ * N_);
    roi_align_kernel<<<grid, 256>>>(boxes, fpn, (float*)d_out);
}